// round 6
// baseline (speedup 1.0000x reference)
#include <cuda_runtime.h>
#include <cuda_bf16.h>
#include <cstdint>

// ============================================================================
// RBM CD-k loss, tensor cores + cp.async pipelining.
// B=16384, D=4096, H=128, k=4.  RNG: jax threefry partitionable (verified).
// R5: double-buffered hidden GEMM, fully-staged visible GEMM, fused bias dots.
// ============================================================================
#define RBM_B 16384
#define RBM_D 4096
#define RBM_H 128

__device__ __nv_bfloat16 g_xb[(size_t)RBM_B * RBM_D];
__device__ __nv_bfloat16 g_xi[(size_t)RBM_B * RBM_D];
__device__ __nv_bfloat16 g_h [(size_t)RBM_B * RBM_H];
__device__ __nv_bfloat16 g_Wp [3][(size_t)RBM_D * RBM_H];   // W split  [d*H+h]
__device__ __nv_bfloat16 g_Wtp[3][(size_t)RBM_H * RBM_D];   // W^T split [h*D+d]
__device__ double g_acc[4];   // [0]=sp(x) [1]=sp(xrec) [2]=x.bx [3]=xrec.bx

// ---------------------------------------------------------------------------
// Threefry-2x32 (verified bit-exact vs jax partitionable mode)
// ---------------------------------------------------------------------------
__device__ __forceinline__ uint2 tf2x32_dev(uint32_t k0, uint32_t k1,
                                            uint32_t x0, uint32_t x1) {
    uint32_t ks2 = k0 ^ k1 ^ 0x1BD11BDAu;
    x0 += k0; x1 += k1;
#define TF_MIX(r) { x0 += x1; x1 = __funnelshift_l(x1, x1, (r)); x1 ^= x0; }
    TF_MIX(13) TF_MIX(15) TF_MIX(26) TF_MIX(6)   x0 += k1;  x1 += ks2 + 1u;
    TF_MIX(17) TF_MIX(29) TF_MIX(16) TF_MIX(24)  x0 += ks2; x1 += k0  + 2u;
    TF_MIX(13) TF_MIX(15) TF_MIX(26) TF_MIX(6)   x0 += k0;  x1 += k1  + 3u;
    TF_MIX(17) TF_MIX(29) TF_MIX(16) TF_MIX(24)  x0 += k1;  x1 += ks2 + 4u;
    TF_MIX(13) TF_MIX(15) TF_MIX(26) TF_MIX(6)   x0 += ks2; x1 += k0  + 5u;
#undef TF_MIX
    return make_uint2(x0, x1);
}
__device__ __forceinline__ float tf_uniform(uint32_t k0, uint32_t k1, uint32_t idx) {
    uint2 o = tf2x32_dev(k0, k1, 0u, idx);
    uint32_t bits = o.x ^ o.y;
    return __uint_as_float((bits >> 9) | 0x3f800000u) - 1.0f;
}
__device__ __forceinline__ float sigmoid_f(float x) { return 1.0f / (1.0f + expf(-x)); }
__device__ __forceinline__ float softplus_f(float x) {
    return fmaxf(x, 0.0f) + log1pf(expf(-fabsf(x)));
}

__device__ __forceinline__ void block_acc_add(float local, int slot) {
    __shared__ float red[8];
    int lane = threadIdx.x & 31, wid = threadIdx.x >> 5;
    #pragma unroll
    for (int off = 16; off; off >>= 1)
        local += __shfl_xor_sync(0xffffffffu, local, off);
    if (lane == 0) red[wid] = local;
    __syncthreads();
    if (threadIdx.x == 0) {
        double s = 0.0;
        #pragma unroll
        for (int i = 0; i < 8; i++) s += (double)red[i];
        atomicAdd(&g_acc[slot], s);
    }
}

// ---------------------------------------------------------------------------
// mma / ldmatrix / cp.async helpers
// ---------------------------------------------------------------------------
__device__ __forceinline__ uint32_t smem_u32(const void* p) {
    uint32_t a;
    asm("{ .reg .u64 t; cvta.to.shared.u64 t, %1; cvt.u32.u64 %0, t; }"
        : "=r"(a) : "l"(p));
    return a;
}
__device__ __forceinline__ void ldsm_x4(uint32_t a, uint32_t& r0, uint32_t& r1,
                                        uint32_t& r2, uint32_t& r3) {
    asm volatile("ldmatrix.sync.aligned.m8n8.x4.shared.b16 {%0,%1,%2,%3}, [%4];"
                 : "=r"(r0), "=r"(r1), "=r"(r2), "=r"(r3) : "r"(a));
}
__device__ __forceinline__ void ldsm_x4_t(uint32_t a, uint32_t& r0, uint32_t& r1,
                                          uint32_t& r2, uint32_t& r3) {
    asm volatile("ldmatrix.sync.aligned.m8n8.x4.trans.shared.b16 {%0,%1,%2,%3}, [%4];"
                 : "=r"(r0), "=r"(r1), "=r"(r2), "=r"(r3) : "r"(a));
}
__device__ __forceinline__ void mma_bf16(float c[4], const uint32_t a[4],
                                         uint32_t b0, uint32_t b1) {
    asm volatile(
        "mma.sync.aligned.m16n8k16.row.col.f32.bf16.bf16.f32 "
        "{%0,%1,%2,%3}, {%4,%5,%6,%7}, {%8,%9}, {%0,%1,%2,%3};"
        : "+f"(c[0]), "+f"(c[1]), "+f"(c[2]), "+f"(c[3])
        : "r"(a[0]), "r"(a[1]), "r"(a[2]), "r"(a[3]), "r"(b0), "r"(b1));
}
__device__ __forceinline__ void cp_async16(uint32_t smem_addr, const void* gptr) {
    asm volatile("cp.async.cg.shared.global [%0], [%1], 16;"
                 :: "r"(smem_addr), "l"(gptr));
}
__device__ __forceinline__ void cp_commit() {
    asm volatile("cp.async.commit_group;" ::: "memory");
}
template<int N> __device__ __forceinline__ void cp_wait() {
    asm volatile("cp.async.wait_group %0;" :: "n"(N) : "memory");
}

// ---------------------------------------------------------------------------
// Hidden GEMM (M=128/CTA, N=128, K=4096), 2-stage cp.async pipeline.
// ---------------------------------------------------------------------------
#define H_AS_STRIDE 72
#define H_BS_STRIDE 136
#define H_AS_ELEMS  (128 * H_AS_STRIDE)                 // 9216
#define H_BS_ELEMS  (64 * H_BS_STRIDE)                  // 8704 / part
#define H_STAGE_ELEMS (H_AS_ELEMS + 3 * H_BS_ELEMS)     // 35328
#define H_SMEM_BYTES  (2 * H_STAGE_ELEMS * 2)           // 141312
#define H_NCHUNK (RBM_D / 64)                           // 64

__global__ void __launch_bounds__(256)
rbm_hidden_mma(int useX0, const float* __restrict__ bh,
               uint32_t k0, uint32_t k1, int doSample, int accIdx) {
    extern __shared__ __align__(16) __nv_bfloat16 sm[];
    __shared__ float bias_s[128];

    const __nv_bfloat16* __restrict__ X = useX0 ? g_xb : g_xi;
    const int tid = threadIdx.x;
    const int lane = tid & 31, w = tid >> 5;
    const int wm = w & 3, wn = w >> 2;
    const int b0 = blockIdx.x * 128;
    if (tid < 128) bias_s[tid] = bh[tid];

    const uint32_t sm_u = smem_u32(sm);

    // stage loader: X tile 128x64 + 3 W-part tiles 64x128
    auto load_stage = [&](int kc, int s) {
        uint32_t sb = sm_u + (uint32_t)(s * H_STAGE_ELEMS * 2);
        #pragma unroll
        for (int p = 0; p < 4; ++p) {
            int lin = tid + p * 256;
            int row = lin >> 3, seg = lin & 7;
            cp_async16(sb + (row * H_AS_STRIDE + seg * 8) * 2,
                       &X[(size_t)(b0 + row) * RBM_D + kc + seg * 8]);
        }
        #pragma unroll
        for (int part = 0; part < 3; ++part) {
            #pragma unroll
            for (int p = 0; p < 4; ++p) {
                int lin = tid + p * 256;
                int row = lin >> 4, seg = lin & 15;
                cp_async16(sb + (H_AS_ELEMS + part * H_BS_ELEMS +
                                 row * H_BS_STRIDE + seg * 8) * 2,
                           &g_Wp[part][(size_t)(kc + row) * RBM_H + seg * 8]);
            }
        }
    };

    float acc[2][8][4];
    #pragma unroll
    for (int mt = 0; mt < 2; mt++)
        #pragma unroll
        for (int nt = 0; nt < 8; nt++)
            #pragma unroll
            for (int e = 0; e < 4; e++) acc[mt][nt][e] = 0.0f;

    const uint32_t a_off = ((wm * 32 + (lane & 15)) * H_AS_STRIDE + (lane >> 4) * 8) * 2;
    const uint32_t b_off = ((lane & 15) * H_BS_STRIDE + wn * 64 + (lane >> 4) * 8) * 2;

    load_stage(0, 0);
    cp_commit();

    for (int c = 0; c < H_NCHUNK; ++c) {
        const int cur = c & 1;
        if (c + 1 < H_NCHUNK) {
            load_stage((c + 1) * 64, cur ^ 1);
            cp_commit();
            cp_wait<1>();
        } else {
            cp_wait<0>();
        }
        __syncthreads();

        const uint32_t sb = sm_u + (uint32_t)(cur * H_STAGE_ELEMS * 2);
        #pragma unroll
        for (int ks = 0; ks < 4; ++ks) {
            uint32_t a[2][4];
            #pragma unroll
            for (int mt = 0; mt < 2; ++mt)
                ldsm_x4(sb + a_off + (mt * 16 * H_AS_STRIDE + ks * 16) * 2,
                        a[mt][0], a[mt][1], a[mt][2], a[mt][3]);
            #pragma unroll
            for (int part = 0; part < 3; ++part) {
                #pragma unroll
                for (int np = 0; np < 4; ++np) {
                    uint32_t r0, r1, r2, r3;
                    ldsm_x4_t(sb + (H_AS_ELEMS + part * H_BS_ELEMS) * 2 + b_off +
                              (ks * 16 * H_BS_STRIDE + np * 16) * 2, r0, r1, r2, r3);
                    mma_bf16(acc[0][np * 2],     a[0], r0, r1);
                    mma_bf16(acc[0][np * 2 + 1], a[0], r2, r3);
                    mma_bf16(acc[1][np * 2],     a[1], r0, r1);
                    mma_bf16(acc[1][np * 2 + 1], a[1], r2, r3);
                }
            }
        }
        __syncthreads();   // protect buffer (c%2) before iter c+1 prefetches into it
    }

    // epilogue
    const __nv_bfloat16 one = __float2bfloat16(1.0f);
    const __nv_bfloat16 zero = __float2bfloat16(0.0f);
    float fe = 0.0f;
    #pragma unroll
    for (int mt = 0; mt < 2; ++mt) {
        #pragma unroll
        for (int nt = 0; nt < 8; ++nt) {
            int row0 = b0 + wm * 32 + mt * 16 + (lane >> 2);
            int col0 = wn * 64 + nt * 8 + (lane & 3) * 2;
            #pragma unroll
            for (int half = 0; half < 2; ++half) {
                int row = row0 + half * 8;
                float wx0 = acc[mt][nt][half * 2 + 0] + bias_s[col0];
                float wx1 = acc[mt][nt][half * 2 + 1] + bias_s[col0 + 1];
                if (doSample) {
                    float u0 = tf_uniform(k0, k1, (uint32_t)(row * RBM_H + col0));
                    float u1 = tf_uniform(k0, k1, (uint32_t)(row * RBM_H + col0 + 1));
                    __nv_bfloat162 v;
                    v.x = (u0 < sigmoid_f(wx0)) ? one : zero;
                    v.y = (u1 < sigmoid_f(wx1)) ? one : zero;
                    *(__nv_bfloat162*)&g_h[(size_t)row * RBM_H + col0] = v;
                }
                if (accIdx >= 0) fe += softplus_f(wx0) + softplus_f(wx1);
            }
        }
    }
    if (accIdx >= 0) block_acc_add(fe, accIdx);
}

// ---------------------------------------------------------------------------
// Visible GEMM (M=128, N=128/CTA, K=128): whole K staged upfront, no mid syncs.
// ---------------------------------------------------------------------------
#define V_STRIDE 136
#define V_AS_ELEMS (128 * V_STRIDE)   // h tile 128x128
#define V_BS_ELEMS (128 * V_STRIDE)   // per part
#define V_SMEM_BYTES ((V_AS_ELEMS + 3 * V_BS_ELEMS) * 2)   // 139264

__global__ void __launch_bounds__(256)
rbm_visible_mma(const float* __restrict__ bx, uint32_t k0, uint32_t k1, int doDot) {
    extern __shared__ __align__(16) __nv_bfloat16 sm[];
    __shared__ float bias_s[128];

    const int tid = threadIdx.x;
    const int lane = tid & 31, w = tid >> 5;
    const int wm = w & 3, wn = w >> 2;
    const int d0 = blockIdx.x * 128;
    const int b0 = blockIdx.y * 128;
    if (tid < 128) bias_s[tid] = bx[d0 + tid];

    const uint32_t sm_u = smem_u32(sm);

    // stage A (g_h tile 128x128) and B (3 parts, 128k x 128n)
    #pragma unroll
    for (int p = 0; p < 8; ++p) {
        int lin = tid + p * 256;
        int row = lin >> 4, seg = lin & 15;
        cp_async16(sm_u + (row * V_STRIDE + seg * 8) * 2,
                   &g_h[(size_t)(b0 + row) * RBM_H + seg * 8]);
    }
    #pragma unroll
    for (int part = 0; part < 3; ++part) {
        #pragma unroll
        for (int p = 0; p < 8; ++p) {
            int lin = tid + p * 256;
            int row = lin >> 4, seg = lin & 15;
            cp_async16(sm_u + (V_AS_ELEMS + part * V_BS_ELEMS +
                               row * V_STRIDE + seg * 8) * 2,
                       &g_Wtp[part][(size_t)row * RBM_D + d0 + seg * 8]);
        }
    }
    cp_commit();

    float acc[2][8][4];
    #pragma unroll
    for (int mt = 0; mt < 2; mt++)
        #pragma unroll
        for (int nt = 0; nt < 8; nt++)
            #pragma unroll
            for (int e = 0; e < 4; e++) acc[mt][nt][e] = 0.0f;

    const uint32_t a_off = ((wm * 32 + (lane & 15)) * V_STRIDE + (lane >> 4) * 8) * 2;
    const uint32_t b_off = ((lane & 15) * V_STRIDE + wn * 64 + (lane >> 4) * 8) * 2;

    cp_wait<0>();
    __syncthreads();

    #pragma unroll
    for (int ks = 0; ks < 8; ++ks) {
        uint32_t a[2][4];
        #pragma unroll
        for (int mt = 0; mt < 2; ++mt)
            ldsm_x4(sm_u + a_off + (mt * 16 * V_STRIDE + ks * 16) * 2,
                    a[mt][0], a[mt][1], a[mt][2], a[mt][3]);
        #pragma unroll
        for (int part = 0; part < 3; ++part) {
            #pragma unroll
            for (int np = 0; np < 4; ++np) {
                uint32_t r0, r1, r2, r3;
                ldsm_x4_t(sm_u + (V_AS_ELEMS + part * V_BS_ELEMS) * 2 + b_off +
                          (ks * 16 * V_STRIDE + np * 16) * 2, r0, r1, r2, r3);
                mma_bf16(acc[0][np * 2],     a[0], r0, r1);
                mma_bf16(acc[0][np * 2 + 1], a[0], r2, r3);
                mma_bf16(acc[1][np * 2],     a[1], r0, r1);
                mma_bf16(acc[1][np * 2 + 1], a[1], r2, r3);
            }
        }
    }

    // epilogue: sample xi; optionally accumulate dot(x_rec, bx)
    const __nv_bfloat16 one = __float2bfloat16(1.0f);
    const __nv_bfloat16 zero = __float2bfloat16(0.0f);
    float dotl = 0.0f;
    #pragma unroll
    for (int mt = 0; mt < 2; ++mt) {
        #pragma unroll
        for (int nt = 0; nt < 8; ++nt) {
            int row0 = b0 + wm * 32 + mt * 16 + (lane >> 2);
            int col0 = wn * 64 + nt * 8 + (lane & 3) * 2;
            #pragma unroll
            for (int half = 0; half < 2; ++half) {
                int b = row0 + half * 8;
                int d = d0 + col0;
                float wx0 = acc[mt][nt][half * 2 + 0] + bias_s[col0];
                float wx1 = acc[mt][nt][half * 2 + 1] + bias_s[col0 + 1];
                uint32_t base = (uint32_t)b * (uint32_t)RBM_D + (uint32_t)d;
                float u0 = tf_uniform(k0, k1, base);
                float u1 = tf_uniform(k0, k1, base + 1u);
                bool s0 = u0 < sigmoid_f(wx0);
                bool s1 = u1 < sigmoid_f(wx1);
                __nv_bfloat162 v;
                v.x = s0 ? one : zero;
                v.y = s1 ? one : zero;
                *(__nv_bfloat162*)&g_xi[(size_t)b * RBM_D + d] = v;
                if (doDot) {
                    if (s0) dotl += bias_s[col0];
                    if (s1) dotl += bias_s[col0 + 1];
                }
            }
        }
    }
    if (doDot) block_acc_add(dotl, 3);
}

// ---------------------------------------------------------------------------
// Prep: exact 3-term bf16 split of W (+ transpose)
// ---------------------------------------------------------------------------
__global__ void __launch_bounds__(256)
rbm_prep_w(const float* __restrict__ W) {
    int i = blockIdx.x * 256 + threadIdx.x;
    if (i >= RBM_D * RBM_H) return;
    float w = W[i];
    __nv_bfloat16 h1 = __float2bfloat16(w);
    float r1 = w - __bfloat162float(h1);
    __nv_bfloat16 h2 = __float2bfloat16(r1);
    float r2 = r1 - __bfloat162float(h2);
    __nv_bfloat16 h3 = __float2bfloat16(r2);
    g_Wp[0][i] = h1; g_Wp[1][i] = h2; g_Wp[2][i] = h3;
    int r = i >> 7, c = i & 127;
    size_t t = (size_t)c * RBM_D + r;
    g_Wtp[0][t] = h1; g_Wtp[1][t] = h2; g_Wtp[2][t] = h3;
}

// x -> bf16, fused with dot(x, bx) into slot 2
__global__ void __launch_bounds__(256)
rbm_convert_x(const float* __restrict__ x, const float* __restrict__ bx) {
    const size_t nchunk = (size_t)RBM_B * RBM_D / 8;
    float local = 0.0f;
    for (size_t c = (size_t)blockIdx.x * 256 + threadIdx.x;
         c < nchunk; c += (size_t)gridDim.x * 256) {
        size_t i = c * 8;
        float4 f0 = *(const float4*)&x[i];
        float4 f1 = *(const float4*)&x[i + 4];
        __nv_bfloat162 r0 = __floats2bfloat162_rn(f0.x, f0.y);
        __nv_bfloat162 r1 = __floats2bfloat162_rn(f0.z, f0.w);
        __nv_bfloat162 r2 = __floats2bfloat162_rn(f1.x, f1.y);
        __nv_bfloat162 r3 = __floats2bfloat162_rn(f1.z, f1.w);
        uint4 o;
        o.x = *(uint32_t*)&r0; o.y = *(uint32_t*)&r1;
        o.z = *(uint32_t*)&r2; o.w = *(uint32_t*)&r3;
        *(uint4*)&g_xb[i] = o;
        uint32_t bxi = (uint32_t)(i & (RBM_D - 1));
        local += f0.x * bx[bxi]     + f0.y * bx[bxi + 1] +
                 f0.z * bx[bxi + 2] + f0.w * bx[bxi + 3] +
                 f1.x * bx[bxi + 4] + f1.y * bx[bxi + 5] +
                 f1.z * bx[bxi + 6] + f1.w * bx[bxi + 7];
    }
    block_acc_add(local, 2);
}

__global__ void rbm_init_kernel() {
    if (threadIdx.x < 4) g_acc[threadIdx.x] = 0.0;
}
__global__ void rbm_final_kernel(float* out) {
    out[0] = (float)((g_acc[1] + g_acc[3] - g_acc[0] - g_acc[2]) * (1.0 / (double)RBM_B));
}

// ---------------------------------------------------------------------------
// Host threefry for fold_in subkeys
// ---------------------------------------------------------------------------
static inline uint32_t h_rotl(uint32_t v, int r) { return (v << r) | (v >> (32 - r)); }
static void h_tf2x32(uint32_t k0, uint32_t k1, uint32_t x0, uint32_t x1,
                     uint32_t* o0, uint32_t* o1) {
    uint32_t ks2 = k0 ^ k1 ^ 0x1BD11BDAu;
    x0 += k0; x1 += k1;
    static const int R0[4] = {13, 15, 26, 6}, R1[4] = {17, 29, 16, 24};
    auto round4 = [&](const int* R) {
        for (int i = 0; i < 4; i++) { x0 += x1; x1 = h_rotl(x1, R[i]); x1 ^= x0; }
    };
    round4(R0); x0 += k1;  x1 += ks2 + 1u;
    round4(R1); x0 += ks2; x1 += k0  + 2u;
    round4(R0); x0 += k0;  x1 += k1  + 3u;
    round4(R1); x0 += k1;  x1 += ks2 + 4u;
    round4(R0); x0 += ks2; x1 += k0  + 5u;
    *o0 = x0; *o1 = x1;
}

extern "C" void kernel_launch(void* const* d_in, const int* in_sizes, int n_in,
                              void* d_out, int out_size) {
    const float* x  = (const float*)d_in[0];
    const float* W  = (const float*)d_in[1];
    const float* bx = (const float*)d_in[2];
    const float* bh = (const float*)d_in[3];
    const int NSTEP = 4;
    float* out = (float*)d_out;

    cudaFuncSetAttribute(rbm_hidden_mma,
        cudaFuncAttributeMaxDynamicSharedMemorySize, H_SMEM_BYTES);
    cudaFuncSetAttribute(rbm_visible_mma,
        cudaFuncAttributeMaxDynamicSharedMemorySize, V_SMEM_BYTES);

    uint32_t kk[8][2];
    for (int i = 0; i < 2 * NSTEP; i++)
        h_tf2x32(0u, 42u, 0u, (uint32_t)i, &kk[i][0], &kk[i][1]);

    dim3 hgrd(RBM_B / 128);
    dim3 vgrd(RBM_D / 128, RBM_B / 128);

    rbm_init_kernel<<<1, 32>>>();
    rbm_prep_w<<<(RBM_D * RBM_H) / 256, 256>>>(W);
    rbm_convert_x<<<2048, 256>>>(x, bx);   // + dot(x,bx) -> slot 2

    rbm_hidden_mma<<<hgrd, 256, H_SMEM_BYTES>>>(1, bh, kk[0][0], kk[0][1], 1, 0);
    rbm_visible_mma<<<vgrd, 256, V_SMEM_BYTES>>>(bx, kk[1][0], kk[1][1], 0);
    for (int s = 1; s < NSTEP; s++) {
        rbm_hidden_mma<<<hgrd, 256, H_SMEM_BYTES>>>(0, bh, kk[2 * s][0], kk[2 * s][1], 1, -1);
        rbm_visible_mma<<<vgrd, 256, V_SMEM_BYTES>>>(bx, kk[2 * s + 1][0], kk[2 * s + 1][1],
                                                     (s == NSTEP - 1) ? 1 : 0);
    }
    rbm_hidden_mma<<<hgrd, 256, H_SMEM_BYTES>>>(0, bh, 0u, 0u, 0, 1);

    rbm_final_kernel<<<1, 1>>>(out);
}